// round 1
// baseline (speedup 1.0000x reference)
#include <cuda_runtime.h>

#define B_  4
#define T_  2048
#define D_  512
#define H_  8
#define HD_ 64
#define BH_ (B_*H_)   // 32

// Scratch (allocation-free rule: __device__ globals)
__device__ __align__(16) float g_Q[BH_*T_*HD_];   // [b,h,t,hd]
__device__ __align__(16) float g_K[BH_*T_*HD_];
__device__ __align__(16) float g_V[BH_*T_*HD_];
__device__ __align__(16) float g_A[B_*T_*D_];     // attention out [b,t,D]

// ---------------------------------------------------------------------------
// GEMM 1: qkv = x @ W_qkv + b_qkv, scattered into g_Q/g_K/g_V [b,h,t,hd]
// M=8192, K=512, N=1536. 128x128x8 tiles, 256 threads, 8x8 per thread.
// ---------------------------------------------------------------------------
__global__ __launch_bounds__(256, 2) void sgemm_qkv(
    const float* __restrict__ X,     // [8192, 512]
    const float* __restrict__ W,     // [512, 1536]
    const float* __restrict__ bias)  // [1536]
{
    const int K = 512, N = 1536;
    __shared__ float As[8][128];
    __shared__ float Bs[8][128];

    int bm = blockIdx.y * 128;
    int bn = blockIdx.x * 128;
    int tid = threadIdx.x;
    int arow = tid >> 1, acol = (tid & 1) << 2;
    int brow = tid >> 5, bcol = (tid & 31) << 2;
    int ty = tid >> 4, tx = tid & 15;

    float acc[8][8];
    #pragma unroll
    for (int i = 0; i < 8; i++)
        #pragma unroll
        for (int j = 0; j < 8; j++) acc[i][j] = 0.0f;

    const float* Xp = X + (bm + arow) * K + acol;
    const float* Wp = W + brow * N + bn + bcol;

    for (int k0 = 0; k0 < K; k0 += 8) {
        float4 av = *(const float4*)(Xp + k0);
        float4 bv = *(const float4*)(Wp + k0 * N);
        As[acol + 0][arow] = av.x;
        As[acol + 1][arow] = av.y;
        As[acol + 2][arow] = av.z;
        As[acol + 3][arow] = av.w;
        *(float4*)&Bs[brow][bcol] = bv;
        __syncthreads();

        #pragma unroll
        for (int kk = 0; kk < 8; kk++) {
            float4 a0 = *(const float4*)&As[kk][ty << 2];
            float4 a1 = *(const float4*)&As[kk][64 + (ty << 2)];
            float4 b0 = *(const float4*)&Bs[kk][tx << 2];
            float4 b1 = *(const float4*)&Bs[kk][64 + (tx << 2)];
            float ar[8] = {a0.x, a0.y, a0.z, a0.w, a1.x, a1.y, a1.z, a1.w};
            float br[8] = {b0.x, b0.y, b0.z, b0.w, b1.x, b1.y, b1.z, b1.w};
            #pragma unroll
            for (int i = 0; i < 8; i++)
                #pragma unroll
                for (int j = 0; j < 8; j++)
                    acc[i][j] += ar[i] * br[j];
        }
        __syncthreads();
    }

    // Epilogue: add bias, scatter to Q/K/V in [b,h,t,hd]
    #pragma unroll
    for (int i = 0; i < 8; i++) {
        int m = bm + ((i >> 2) << 6) + (ty << 2) + (i & 3);
        int b = m >> 11;            // /2048
        int t = m & (T_ - 1);
        #pragma unroll
        for (int j = 0; j < 8; j++) {
            int n = bn + ((j >> 2) << 6) + (tx << 2) + (j & 3);
            float v = acc[i][j] + bias[n];
            int which = n >> 9;     // 0=q, 1=k, 2=v
            int r = n & 511;
            int h = r >> 6, hd = r & 63;
            float* dst = (which == 0) ? g_Q : ((which == 1) ? g_K : g_V);
            dst[((b * H_ + h) * T_ + t) * HD_ + hd] = v;
        }
    }
}

// ---------------------------------------------------------------------------
// GEMM 2: out = g_A @ W_out + b_out. M=8192, K=512, N=512.
// ---------------------------------------------------------------------------
__global__ __launch_bounds__(256, 2) void sgemm_out(
    const float* __restrict__ W,     // [512, 512]
    const float* __restrict__ bias,  // [512]
    float* __restrict__ out)         // [8192, 512]
{
    const int K = 512, N = 512;
    __shared__ float As[8][128];
    __shared__ float Bs[8][128];

    int bm = blockIdx.y * 128;
    int bn = blockIdx.x * 128;
    int tid = threadIdx.x;
    int arow = tid >> 1, acol = (tid & 1) << 2;
    int brow = tid >> 5, bcol = (tid & 31) << 2;
    int ty = tid >> 4, tx = tid & 15;

    float acc[8][8];
    #pragma unroll
    for (int i = 0; i < 8; i++)
        #pragma unroll
        for (int j = 0; j < 8; j++) acc[i][j] = 0.0f;

    const float* Xp = g_A + (bm + arow) * K + acol;
    const float* Wp = W + brow * N + bn + bcol;

    for (int k0 = 0; k0 < K; k0 += 8) {
        float4 av = *(const float4*)(Xp + k0);
        float4 bv = *(const float4*)(Wp + k0 * N);
        As[acol + 0][arow] = av.x;
        As[acol + 1][arow] = av.y;
        As[acol + 2][arow] = av.z;
        As[acol + 3][arow] = av.w;
        *(float4*)&Bs[brow][bcol] = bv;
        __syncthreads();

        #pragma unroll
        for (int kk = 0; kk < 8; kk++) {
            float4 a0 = *(const float4*)&As[kk][ty << 2];
            float4 a1 = *(const float4*)&As[kk][64 + (ty << 2)];
            float4 b0 = *(const float4*)&Bs[kk][tx << 2];
            float4 b1 = *(const float4*)&Bs[kk][64 + (tx << 2)];
            float ar[8] = {a0.x, a0.y, a0.z, a0.w, a1.x, a1.y, a1.z, a1.w};
            float br[8] = {b0.x, b0.y, b0.z, b0.w, b1.x, b1.y, b1.z, b1.w};
            #pragma unroll
            for (int i = 0; i < 8; i++)
                #pragma unroll
                for (int j = 0; j < 8; j++)
                    acc[i][j] += ar[i] * br[j];
        }
        __syncthreads();
    }

    #pragma unroll
    for (int i = 0; i < 8; i++) {
        int m = bm + ((i >> 2) << 6) + (ty << 2) + (i & 3);
        #pragma unroll
        for (int j = 0; j < 8; j++) {
            int n = bn + ((j >> 2) << 6) + (tx << 2) + (j & 3);
            out[m * N + n] = acc[i][j] + bias[n];
        }
    }
}

// ---------------------------------------------------------------------------
// Flash attention (causal). Grid: (qtile=32, bh=32). 256 threads (16x16).
// Q tile 64 rows, K/V tiles 32 rows, Hd=64. Online softmax.
// Static smem: 64*65 + 32*65 + 32*65 + 64*33 floats = ~42 KB.
// ---------------------------------------------------------------------------
__global__ __launch_bounds__(256, 2) void attn_kernel()
{
    __shared__ float Qs[64][65];
    __shared__ float Ks[32][65];
    __shared__ float Vs[32][65];
    __shared__ float Ps[64][33];

    int qt = blockIdx.x;      // q tile: 0..31
    int bh = blockIdx.y;      // 0..31
    int tid = threadIdx.x;
    int ty = tid >> 4, tx = tid & 15;
    int q0 = qt * 64;

    const float* Qp = g_Q + (size_t)bh * T_ * HD_;
    const float* Kp = g_K + (size_t)bh * T_ * HD_;
    const float* Vp = g_V + (size_t)bh * T_ * HD_;

    // Load Q tile, fold in 1/sqrt(Hd) = 0.125
    for (int idx = tid; idx < 64 * 16; idx += 256) {
        int row = idx >> 4, c4 = (idx & 15) << 2;
        float4 v = *(const float4*)&Qp[(q0 + row) * HD_ + c4];
        Qs[row][c4 + 0] = v.x * 0.125f;
        Qs[row][c4 + 1] = v.y * 0.125f;
        Qs[row][c4 + 2] = v.z * 0.125f;
        Qs[row][c4 + 3] = v.w * 0.125f;
    }

    float O[4][4];
    float mrow[4], lrow[4];
    #pragma unroll
    for (int r = 0; r < 4; r++) {
        mrow[r] = -1e30f;
        lrow[r] = 0.0f;
        #pragma unroll
        for (int c = 0; c < 4; c++) O[r][c] = 0.0f;
    }

    int ktmax = 2 * qt + 1;
    for (int kt = 0; kt <= ktmax; kt++) {
        int j0 = kt * 32;
        __syncthreads();   // protect Ks/Vs/Ps from previous iteration

        // Load K and V tiles: 32 rows x 64 cols each
        for (int idx = tid; idx < 512; idx += 256) {
            int row = idx >> 4, c4 = (idx & 15) << 2;
            float4 kv = *(const float4*)&Kp[(j0 + row) * HD_ + c4];
            Ks[row][c4 + 0] = kv.x;
            Ks[row][c4 + 1] = kv.y;
            Ks[row][c4 + 2] = kv.z;
            Ks[row][c4 + 3] = kv.w;
            float4 vv = *(const float4*)&Vp[(j0 + row) * HD_ + c4];
            Vs[row][c4 + 0] = vv.x;
            Vs[row][c4 + 1] = vv.y;
            Vs[row][c4 + 2] = vv.z;
            Vs[row][c4 + 3] = vv.w;
        }
        __syncthreads();

        // S tile: rows 4*ty+r (64), cols 2*tx+c (32)
        float s[4][2] = {{0.f,0.f},{0.f,0.f},{0.f,0.f},{0.f,0.f}};
        #pragma unroll 16
        for (int d = 0; d < 64; d++) {
            float kv0 = Ks[2 * tx + 0][d];
            float kv1 = Ks[2 * tx + 1][d];
            #pragma unroll
            for (int r = 0; r < 4; r++) {
                float qv = Qs[4 * ty + r][d];
                s[r][0] += qv * kv0;
                s[r][1] += qv * kv1;
            }
        }

        // Causal mask (only the last two tiles of each q-tile can be masked)
        if (j0 + 31 > q0) {
            #pragma unroll
            for (int r = 0; r < 4; r++) {
                int qi = q0 + 4 * ty + r;
                #pragma unroll
                for (int c = 0; c < 2; c++) {
                    int kj = j0 + 2 * tx + c;
                    if (kj > qi) s[r][c] = -1e30f;
                }
            }
        }

        // Online softmax per row (16 tx lanes own each row group)
        #pragma unroll
        for (int r = 0; r < 4; r++) {
            float v = fmaxf(s[r][0], s[r][1]);
            v = fmaxf(v, __shfl_xor_sync(0xffffffffu, v, 8, 16));
            v = fmaxf(v, __shfl_xor_sync(0xffffffffu, v, 4, 16));
            v = fmaxf(v, __shfl_xor_sync(0xffffffffu, v, 2, 16));
            v = fmaxf(v, __shfl_xor_sync(0xffffffffu, v, 1, 16));
            float nm = fmaxf(mrow[r], v);
            float fac = __expf(mrow[r] - nm);
            mrow[r] = nm;
            float p0 = __expf(s[r][0] - nm);
            float p1 = __expf(s[r][1] - nm);
            float rs = p0 + p1;
            rs += __shfl_xor_sync(0xffffffffu, rs, 8, 16);
            rs += __shfl_xor_sync(0xffffffffu, rs, 4, 16);
            rs += __shfl_xor_sync(0xffffffffu, rs, 2, 16);
            rs += __shfl_xor_sync(0xffffffffu, rs, 1, 16);
            lrow[r] = lrow[r] * fac + rs;
            Ps[4 * ty + r][2 * tx + 0] = p0;
            Ps[4 * ty + r][2 * tx + 1] = p1;
            #pragma unroll
            for (int c = 0; c < 4; c++) O[r][c] *= fac;
        }
        __syncthreads();

        // O += P @ V : rows 4*ty+r, cols 4*tx+c
        #pragma unroll 8
        for (int j = 0; j < 32; j++) {
            float vv[4];
            #pragma unroll
            for (int c = 0; c < 4; c++) vv[c] = Vs[j][4 * tx + c];
            #pragma unroll
            for (int r = 0; r < 4; r++) {
                float pv = Ps[4 * ty + r][j];
                #pragma unroll
                for (int c = 0; c < 4; c++) O[r][c] += pv * vv[c];
            }
        }
    }

    // Epilogue: normalize, write to g_A[b, t, h*64 + hd]
    int b = bh >> 3, h = bh & 7;
    #pragma unroll
    for (int r = 0; r < 4; r++) {
        float inv = 1.0f / lrow[r];
        int t = q0 + 4 * ty + r;
        float4 v = make_float4(O[r][0] * inv, O[r][1] * inv,
                               O[r][2] * inv, O[r][3] * inv);
        *(float4*)&g_A[(b * T_ + t) * D_ + h * HD_ + 4 * tx] = v;
    }
}

// ---------------------------------------------------------------------------
extern "C" void kernel_launch(void* const* d_in, const int* in_sizes, int n_in,
                              void* d_out, int out_size)
{
    const float* x     = (const float*)d_in[0];   // [4,2048,512]
    const float* W_qkv = (const float*)d_in[1];   // [512,1536]
    const float* b_qkv = (const float*)d_in[2];   // [1536]
    const float* W_out = (const float*)d_in[3];   // [512,512]
    const float* b_out = (const float*)d_in[4];   // [512]
    float* out = (float*)d_out;                   // [4,2048,512]

    sgemm_qkv<<<dim3(12, 64), 256>>>(x, W_qkv, b_qkv);
    attn_kernel<<<dim3(32, 32), 256>>>();
    sgemm_out<<<dim3(4, 64), 256>>>(W_out, b_out, out);
}

// round 3
// speedup vs baseline: 1.7668x; 1.7668x over previous
#include <cuda_runtime.h>
#include <cuda_bf16.h>

#define B_  4
#define T_  2048
#define D_  512
#define H_  8
#define HD_ 64
#define BH_ (B_*H_)   // 32

// Scratch (allocation-free rule: __device__ globals)
__device__ __align__(16) float g_Qf[BH_*T_*HD_];   // [b,h,t,hd] tf32-rounded, pre-scaled 0.125
__device__ __align__(16) float g_Kt[BH_*HD_*T_];   // [b,h,hd,t] tf32-rounded (transposed)
__device__ __align__(16) float g_Vt[BH_*HD_*T_];   // [b,h,dv,t] tf32-rounded (transposed)
__device__ __align__(16) float g_A [B_*T_*D_];     // attention out [b,t,D]

__device__ __forceinline__ float to_tf32(float x) {
    float r;
    asm("cvt.rna.tf32.f32 %0, %1;" : "=f"(r) : "f"(x));
    return r;
}

__device__ __forceinline__ void mma_tf32(float* c, const float* a, float b0, float b1) {
    asm volatile(
        "mma.sync.aligned.m16n8k8.row.col.f32.tf32.tf32.f32 "
        "{%0,%1,%2,%3},{%4,%5,%6,%7},{%8,%9},{%0,%1,%2,%3};"
        : "+f"(c[0]), "+f"(c[1]), "+f"(c[2]), "+f"(c[3])
        : "r"(__float_as_uint(a[0])), "r"(__float_as_uint(a[1])),
          "r"(__float_as_uint(a[2])), "r"(__float_as_uint(a[3])),
          "r"(__float_as_uint(b0)), "r"(__float_as_uint(b1)));
}

// ---------------------------------------------------------------------------
// GEMM 1: qkv = x @ W_qkv + b_qkv -> Qf (tf32, scaled), Kt/Vt (tf32, transposed)
// ---------------------------------------------------------------------------
__global__ __launch_bounds__(256, 2) void sgemm_qkv(
    const float* __restrict__ X,     // [8192, 512]
    const float* __restrict__ W,     // [512, 1536]
    const float* __restrict__ bias)  // [1536]
{
    const int K = 512, N = 1536;
    __shared__ float As[8][128];
    __shared__ float Bs[8][128];

    int bm = blockIdx.y * 128;
    int bn = blockIdx.x * 128;
    int tid = threadIdx.x;
    int arow = tid >> 1, acol = (tid & 1) << 2;
    int brow = tid >> 5, bcol = (tid & 31) << 2;
    int ty = tid >> 4, tx = tid & 15;

    float acc[8][8];
    #pragma unroll
    for (int i = 0; i < 8; i++)
        #pragma unroll
        for (int j = 0; j < 8; j++) acc[i][j] = 0.0f;

    const float* Xp = X + (bm + arow) * K + acol;
    const float* Wp = W + brow * N + bn + bcol;

    for (int k0 = 0; k0 < K; k0 += 8) {
        float4 av = *(const float4*)(Xp + k0);
        float4 bv = *(const float4*)(Wp + k0 * N);
        As[acol + 0][arow] = av.x;
        As[acol + 1][arow] = av.y;
        As[acol + 2][arow] = av.z;
        As[acol + 3][arow] = av.w;
        *(float4*)&Bs[brow][bcol] = bv;
        __syncthreads();

        #pragma unroll
        for (int kk = 0; kk < 8; kk++) {
            float4 a0 = *(const float4*)&As[kk][ty << 2];
            float4 a1 = *(const float4*)&As[kk][64 + (ty << 2)];
            float4 b0 = *(const float4*)&Bs[kk][tx << 2];
            float4 b1 = *(const float4*)&Bs[kk][64 + (tx << 2)];
            float ar[8] = {a0.x, a0.y, a0.z, a0.w, a1.x, a1.y, a1.z, a1.w};
            float br[8] = {b0.x, b0.y, b0.z, b0.w, b1.x, b1.y, b1.z, b1.w};
            #pragma unroll
            for (int i = 0; i < 8; i++)
                #pragma unroll
                for (int j = 0; j < 8; j++)
                    acc[i][j] += ar[i] * br[j];
        }
        __syncthreads();
    }

    // Epilogue: bias, then scatter to Qf / Kt / Vt
    #pragma unroll
    for (int i = 0; i < 8; i++) {
        int m = bm + ((i >> 2) << 6) + (ty << 2) + (i & 3);
        int b = m >> 11;
        int t = m & (T_ - 1);
        #pragma unroll
        for (int j = 0; j < 8; j++) {
            int n = bn + ((j >> 2) << 6) + (tx << 2) + (j & 3);
            float v = acc[i][j] + bias[n];
            int which = n >> 9;     // 0=q, 1=k, 2=v
            int r = n & 511;
            int h = r >> 6, hd = r & 63;
            int bh = b * H_ + h;
            if (which == 0)
                g_Qf[((size_t)bh * T_ + t) * HD_ + hd] = to_tf32(v * 0.125f);
            else if (which == 1)
                g_Kt[((size_t)bh * HD_ + hd) * T_ + t] = to_tf32(v);
            else
                g_Vt[((size_t)bh * HD_ + hd) * T_ + t] = to_tf32(v);
        }
    }
}

// ---------------------------------------------------------------------------
// GEMM 2: out = g_A @ W_out + b_out. M=8192, K=512, N=512.
// ---------------------------------------------------------------------------
__global__ __launch_bounds__(256, 2) void sgemm_out(
    const float* __restrict__ W,     // [512, 512]
    const float* __restrict__ bias,  // [512]
    float* __restrict__ out)         // [8192, 512]
{
    const int K = 512, N = 512;
    __shared__ float As[8][128];
    __shared__ float Bs[8][128];

    int bm = blockIdx.y * 128;
    int bn = blockIdx.x * 128;
    int tid = threadIdx.x;
    int arow = tid >> 1, acol = (tid & 1) << 2;
    int brow = tid >> 5, bcol = (tid & 31) << 2;
    int ty = tid >> 4, tx = tid & 15;

    float acc[8][8];
    #pragma unroll
    for (int i = 0; i < 8; i++)
        #pragma unroll
        for (int j = 0; j < 8; j++) acc[i][j] = 0.0f;

    const float* Xp = g_A + (bm + arow) * K + acol;
    const float* Wp = W + brow * N + bn + bcol;

    for (int k0 = 0; k0 < K; k0 += 8) {
        float4 av = *(const float4*)(Xp + k0);
        float4 bv = *(const float4*)(Wp + k0 * N);
        As[acol + 0][arow] = av.x;
        As[acol + 1][arow] = av.y;
        As[acol + 2][arow] = av.z;
        As[acol + 3][arow] = av.w;
        *(float4*)&Bs[brow][bcol] = bv;
        __syncthreads();

        #pragma unroll
        for (int kk = 0; kk < 8; kk++) {
            float4 a0 = *(const float4*)&As[kk][ty << 2];
            float4 a1 = *(const float4*)&As[kk][64 + (ty << 2)];
            float4 b0 = *(const float4*)&Bs[kk][tx << 2];
            float4 b1 = *(const float4*)&Bs[kk][64 + (tx << 2)];
            float ar[8] = {a0.x, a0.y, a0.z, a0.w, a1.x, a1.y, a1.z, a1.w};
            float br[8] = {b0.x, b0.y, b0.z, b0.w, b1.x, b1.y, b1.z, b1.w};
            #pragma unroll
            for (int i = 0; i < 8; i++)
                #pragma unroll
                for (int j = 0; j < 8; j++)
                    acc[i][j] += ar[i] * br[j];
        }
        __syncthreads();
    }

    #pragma unroll
    for (int i = 0; i < 8; i++) {
        int m = bm + ((i >> 2) << 6) + (ty << 2) + (i & 3);
        #pragma unroll
        for (int j = 0; j < 8; j++) {
            int n = bn + ((j >> 2) << 6) + (tx << 2) + (j & 3);
            out[m * N + n] = acc[i][j] + bias[n];
        }
    }
}

// ---------------------------------------------------------------------------
// Flash attention (causal), all-tf32 mma.
// Grid: (qtile=16, bh=32). 256 threads = 8 warps; warp w owns Q rows
// [q0+16w, q0+16w+16). KV tiles of 64.
// ---------------------------------------------------------------------------
__global__ __launch_bounds__(256) void attn_mma()
{
    __shared__ float Kst[64][72];   // [d][j]  stride 72: conflict-free for S-phase reads
    __shared__ float Vst[64][68];   // [dv][j] stride 68: conflict-free for PV-phase reads

    int qt = 15 - blockIdx.x;     // big tiles first (load balance)
    int bh = blockIdx.y;
    int tid = threadIdx.x;
    int w = tid >> 5, lane = tid & 31;
    int g = lane >> 2, t4 = lane & 3;
    int q0 = qt * 128;

    int src_lo = (lane & ~3) | (t4 >> 1);
    int src_hi = src_lo + 2;
    bool odd = (t4 & 1) != 0;

    const float* Qp = g_Qf + (size_t)bh * T_ * HD_;
    const float* Kp = g_Kt + (size_t)bh * HD_ * T_;
    const float* Vp = g_Vt + (size_t)bh * HD_ * T_;

    // Q fragments in registers: 8 k-steps x 4 regs
    int r0 = q0 + w * 16 + g;
    float qa[8][4];
    #pragma unroll
    for (int k = 0; k < 8; k++) {
        qa[k][0] = Qp[(size_t)r0 * HD_ + k * 8 + t4];
        qa[k][1] = Qp[(size_t)(r0 + 8) * HD_ + k * 8 + t4];
        qa[k][2] = Qp[(size_t)r0 * HD_ + k * 8 + t4 + 4];
        qa[k][3] = Qp[(size_t)(r0 + 8) * HD_ + k * 8 + t4 + 4];
    }

    float O[8][4];
    #pragma unroll
    for (int n = 0; n < 8; n++)
        #pragma unroll
        for (int c = 0; c < 4; c++) O[n][c] = 0.0f;
    float m0 = -1e30f, m1 = -1e30f, l0 = 0.0f, l1 = 0.0f;

    int nkt = 2 * (qt + 1);
    for (int kt = 0; kt < nkt; kt++) {
        int j0 = kt * 64;
        __syncthreads();

        // Load K^T tile and V^T tile (both fp32, [d][j])
        #pragma unroll
        for (int i = 0; i < 4; i++) {
            int linear = i * 256 + tid;             // 0..1023
            int row = linear >> 4, c4 = (linear & 15) << 2;
            *(float4*)&Kst[row][c4] = *(const float4*)&Kp[(size_t)row * T_ + j0 + c4];
            *(float4*)&Vst[row][c4] = *(const float4*)&Vp[(size_t)row * T_ + j0 + c4];
        }
        __syncthreads();

        // S = Q * K^T  (tf32 mma), S[n] covers cols j0+8n..j0+8n+7
        float S[8][4];
        #pragma unroll
        for (int n = 0; n < 8; n++)
            #pragma unroll
            for (int c = 0; c < 4; c++) S[n][c] = 0.0f;

        #pragma unroll
        for (int k = 0; k < 8; k++) {
            #pragma unroll
            for (int n = 0; n < 8; n++) {
                float b0 = Kst[k * 8 + t4][n * 8 + g];
                float b1 = Kst[k * 8 + t4 + 4][n * 8 + g];
                mma_tf32(S[n], qa[k], b0, b1);
            }
        }

        // Causal mask (only last two tiles can straddle the diagonal)
        if (kt >= nkt - 2) {
            int qi0 = r0, qi1 = r0 + 8;
            #pragma unroll
            for (int n = 0; n < 8; n++) {
                int j = j0 + 8 * n + 2 * t4;
                if (j     > qi0) S[n][0] = -1e30f;
                if (j + 1 > qi0) S[n][1] = -1e30f;
                if (j     > qi1) S[n][2] = -1e30f;
                if (j + 1 > qi1) S[n][3] = -1e30f;
            }
        }

        // Online softmax (rows r0 and r0+8; quad lanes share a row)
        float vmax0 = -1e30f, vmax1 = -1e30f;
        #pragma unroll
        for (int n = 0; n < 8; n++) {
            vmax0 = fmaxf(vmax0, fmaxf(S[n][0], S[n][1]));
            vmax1 = fmaxf(vmax1, fmaxf(S[n][2], S[n][3]));
        }
        vmax0 = fmaxf(vmax0, __shfl_xor_sync(0xffffffffu, vmax0, 1));
        vmax0 = fmaxf(vmax0, __shfl_xor_sync(0xffffffffu, vmax0, 2));
        vmax1 = fmaxf(vmax1, __shfl_xor_sync(0xffffffffu, vmax1, 1));
        vmax1 = fmaxf(vmax1, __shfl_xor_sync(0xffffffffu, vmax1, 2));

        float nm0 = fmaxf(m0, vmax0);
        float nm1 = fmaxf(m1, vmax1);
        float fac0 = __expf(m0 - nm0);
        float fac1 = __expf(m1 - nm1);
        m0 = nm0; m1 = nm1;

        // P = exp(S - m), rounded to tf32; l accumulates the ROUNDED p
        float rs0 = 0.0f, rs1 = 0.0f;
        #pragma unroll
        for (int n = 0; n < 8; n++) {
            float p00 = to_tf32(__expf(S[n][0] - nm0));
            float p01 = to_tf32(__expf(S[n][1] - nm0));
            float p10 = to_tf32(__expf(S[n][2] - nm1));
            float p11 = to_tf32(__expf(S[n][3] - nm1));
            rs0 += p00 + p01;
            rs1 += p10 + p11;
            S[n][0] = p00; S[n][1] = p01; S[n][2] = p10; S[n][3] = p11;
        }
        rs0 += __shfl_xor_sync(0xffffffffu, rs0, 1);
        rs0 += __shfl_xor_sync(0xffffffffu, rs0, 2);
        rs1 += __shfl_xor_sync(0xffffffffu, rs1, 1);
        rs1 += __shfl_xor_sync(0xffffffffu, rs1, 2);
        l0 = l0 * fac0 + rs0;
        l1 = l1 * fac1 + rs1;

        #pragma unroll
        for (int n = 0; n < 8; n++) {
            O[n][0] *= fac0; O[n][1] *= fac0;
            O[n][2] *= fac1; O[n][3] *= fac1;
        }

        // O += P * V  (tf32 mma). Transpose P's C-fragment layout to the
        // A-fragment layout via intra-quad shuffles:
        //   have cols {2t4, 2t4+1}; need cols {t4, t4+4}.
        #pragma unroll
        for (int kk = 0; kk < 8; kk++) {
            float p00 = S[kk][0], p01 = S[kk][1];
            float p10 = S[kk][2], p11 = S[kk][3];
            float x0 = __shfl_sync(0xffffffffu, p00, src_lo);
            float x1 = __shfl_sync(0xffffffffu, p01, src_lo);
            float y0 = __shfl_sync(0xffffffffu, p10, src_lo);
            float y1 = __shfl_sync(0xffffffffu, p11, src_lo);
            float z0 = __shfl_sync(0xffffffffu, p00, src_hi);
            float z1 = __shfl_sync(0xffffffffu, p01, src_hi);
            float u0 = __shfl_sync(0xffffffffu, p10, src_hi);
            float u1 = __shfl_sync(0xffffffffu, p11, src_hi);
            float a[4];
            a[0] = odd ? x1 : x0;   // row g,   col t4
            a[1] = odd ? y1 : y0;   // row g+8, col t4
            a[2] = odd ? z1 : z0;   // row g,   col t4+4
            a[3] = odd ? u1 : u0;   // row g+8, col t4+4
            #pragma unroll
            for (int n = 0; n < 8; n++) {
                float b0 = Vst[8 * n + g][8 * kk + t4];
                float b1 = Vst[8 * n + g][8 * kk + t4 + 4];
                mma_tf32(O[n], a, b0, b1);
            }
        }
    }

    // Epilogue: normalize, write g_A[b, t, h*64 + dv]
    int b = bh >> 3, h = bh & 7;
    float inv0 = 1.0f / l0;
    float inv1 = 1.0f / l1;
    #pragma unroll
    for (int n = 0; n < 8; n++) {
        int dv = 8 * n + 2 * t4;
        float2 v0 = make_float2(O[n][0] * inv0, O[n][1] * inv0);
        float2 v1 = make_float2(O[n][2] * inv1, O[n][3] * inv1);
        *(float2*)&g_A[((size_t)b * T_ + r0)     * D_ + h * HD_ + dv] = v0;
        *(float2*)&g_A[((size_t)b * T_ + r0 + 8) * D_ + h * HD_ + dv] = v1;
    }
}

// ---------------------------------------------------------------------------
extern "C" void kernel_launch(void* const* d_in, const int* in_sizes, int n_in,
                              void* d_out, int out_size)
{
    const float* x     = (const float*)d_in[0];   // [4,2048,512]
    const float* W_qkv = (const float*)d_in[1];   // [512,1536]
    const float* b_qkv = (const float*)d_in[2];   // [1536]
    const float* W_out = (const float*)d_in[3];   // [512,512]
    const float* b_out = (const float*)d_in[4];   // [512]
    float* out = (float*)d_out;                   // [4,2048,512]

    sgemm_qkv<<<dim3(12, 64), 256>>>(x, W_qkv, b_qkv);
    attn_mma<<<dim3(16, 32), 256>>>();
    sgemm_out<<<dim3(4, 64), 256>>>(W_out, b_out, out);
}

// round 5
// speedup vs baseline: 2.6037x; 1.4737x over previous
#include <cuda_runtime.h>
#include <cuda_bf16.h>

#define B_  4
#define T_  2048
#define D_  512
#define H_  8
#define HD_ 64
#define BH_ (B_*H_)   // 32

// Scratch (allocation-free rule: __device__ globals)
__device__ __align__(16) float g_Qf[BH_*T_*HD_];   // [b,h,t,hd] tf32, pre-scaled 0.125
__device__ __align__(16) float g_Kt[BH_*HD_*T_];   // [b,h,hd,t] tf32 (transposed)
__device__ __align__(16) float g_Vt[BH_*HD_*T_];   // [b,h,dv,t] tf32 (transposed)
__device__ __align__(16) float g_A [B_*T_*D_];     // attention out [b,t,D], tf32-rounded

__device__ __forceinline__ float to_tf32(float x) {
    float r;
    asm("cvt.rna.tf32.f32 %0, %1;" : "=f"(r) : "f"(x));
    return r;
}

__device__ __forceinline__ float4 to_tf32_4(float4 v) {
    return make_float4(to_tf32(v.x), to_tf32(v.y), to_tf32(v.z), to_tf32(v.w));
}

__device__ __forceinline__ void mma_tf32(float* c, const float* a, float b0, float b1) {
    asm volatile(
        "mma.sync.aligned.m16n8k8.row.col.f32.tf32.tf32.f32 "
        "{%0,%1,%2,%3},{%4,%5,%6,%7},{%8,%9},{%0,%1,%2,%3};"
        : "+f"(c[0]), "+f"(c[1]), "+f"(c[2]), "+f"(c[3])
        : "r"(__float_as_uint(a[0])), "r"(__float_as_uint(a[1])),
          "r"(__float_as_uint(a[2])), "r"(__float_as_uint(a[3])),
          "r"(__float_as_uint(b0)), "r"(__float_as_uint(b1)));
}

// ===========================================================================
// tf32 mma GEMM core: C[128x128] = A[128xK] * B[Kx128] (+bias in epilogue).
// 256 threads = 8 warps (4m x 2n), warp tile 32x64, k-tile 32.
// EPI: 0 = plain store to out + bias ; 1 = qkv scatter epilogue.
// A_GA: true = read A from device-global g_A (NEVER pass a __device__ symbol
//       as a host-side kernel arg — it resolves to the host shadow address).
// ===========================================================================
template<int N_GL, int EPI, bool A_GA>
__global__ __launch_bounds__(256, 2) void gemm_tf32(
    const float* __restrict__ A_in,
    const float* __restrict__ B_gl,
    const float* __restrict__ bias,
    float* __restrict__ out)
{
    const int K = 512;
    const float* A_gl = A_GA ? (const float*)g_A : A_in;

    __shared__ float As[128][36];    // [m][k], stride 36 (== 4 mod 32)
    __shared__ float Bs[32][136];    // [k][n], stride 136 (== 8 mod 32)

    int bm = blockIdx.y * 128, bn = blockIdx.x * 128;
    int tid = threadIdx.x;
    int w = tid >> 5, lane = tid & 31, g = lane >> 2, t4 = lane & 3;
    int wm = (w >> 1) * 32, wn = (w & 1) * 64;

    // gmem tile-load coordinates
    int ar = tid >> 1;               // 0..127
    int ak = (tid & 1) * 16;         // + i*4
    int br = tid >> 3;               // 0..31
    int bc = (tid & 7) * 16;         // + i*4

    const float* Ap = A_gl + (size_t)(bm + ar) * K + ak;
    const float* Bp = B_gl + (size_t)br * N_GL + bn + bc;

    float4 ra[4], rb[4];
    #pragma unroll
    for (int i = 0; i < 4; i++) {
        ra[i] = *(const float4*)(Ap + i * 4);
        rb[i] = *(const float4*)(Bp + i * 4);
    }

    float acc[2][8][4];
    #pragma unroll
    for (int mt = 0; mt < 2; mt++)
        #pragma unroll
        for (int nt = 0; nt < 8; nt++)
            #pragma unroll
            for (int c = 0; c < 4; c++) acc[mt][nt][c] = 0.0f;

    #pragma unroll 1
    for (int kt = 0; kt < 16; kt++) {
        // store current tile (tf32-rounded)
        #pragma unroll
        for (int i = 0; i < 4; i++) {
            *(float4*)&As[ar][ak + i * 4] = to_tf32_4(ra[i]);
            *(float4*)&Bs[br][bc + i * 4] = to_tf32_4(rb[i]);
        }
        __syncthreads();

        // prefetch next tile
        if (kt < 15) {
            Ap += 32;
            Bp += (size_t)32 * N_GL;
            #pragma unroll
            for (int i = 0; i < 4; i++) {
                ra[i] = *(const float4*)(Ap + i * 4);
                rb[i] = *(const float4*)(Bp + i * 4);
            }
        }

        // compute 4 k-steps of 8
        #pragma unroll
        for (int ks = 0; ks < 4; ks++) {
            int k0 = ks * 8;
            float af[2][4];
            #pragma unroll
            for (int mt = 0; mt < 2; mt++) {
                af[mt][0] = As[wm + mt * 16 + g][k0 + t4];
                af[mt][1] = As[wm + mt * 16 + g + 8][k0 + t4];
                af[mt][2] = As[wm + mt * 16 + g][k0 + t4 + 4];
                af[mt][3] = As[wm + mt * 16 + g + 8][k0 + t4 + 4];
            }
            #pragma unroll
            for (int nt = 0; nt < 8; nt++) {
                float b0 = Bs[k0 + t4][wn + nt * 8 + g];
                float b1 = Bs[k0 + t4 + 4][wn + nt * 8 + g];
                mma_tf32(acc[0][nt], af[0], b0, b1);
                mma_tf32(acc[1][nt], af[1], b0, b1);
            }
        }
        __syncthreads();
    }

    // Epilogue
    #pragma unroll
    for (int mt = 0; mt < 2; mt++) {
        #pragma unroll
        for (int nt = 0; nt < 8; nt++) {
            #pragma unroll
            for (int c = 0; c < 4; c++) {
                int m = bm + wm + mt * 16 + g + ((c >> 1) ? 8 : 0);
                int n = bn + wn + nt * 8 + 2 * t4 + (c & 1);
                float v = acc[mt][nt][c] + bias[n];
                if (EPI == 0) {
                    out[(size_t)m * N_GL + n] = v;
                } else {
                    int b = m >> 11;
                    int t = m & (T_ - 1);
                    int which = n >> 9;     // 0=q, 1=k, 2=v
                    int r = n & 511;
                    int h = r >> 6, hd = r & 63;
                    int bh = b * H_ + h;
                    if (which == 0)
                        g_Qf[((size_t)bh * T_ + t) * HD_ + hd] = to_tf32(v * 0.125f);
                    else if (which == 1)
                        g_Kt[((size_t)bh * HD_ + hd) * T_ + t] = to_tf32(v);
                    else
                        g_Vt[((size_t)bh * HD_ + hd) * T_ + t] = to_tf32(v);
                }
            }
        }
    }
}

// ---------------------------------------------------------------------------
// Flash attention (causal), all-tf32 mma.
// Grid: (qtile=16, bh=32). 256 threads = 8 warps; warp w owns Q rows
// [q0+16w, q0+16w+16). KV tiles of 64.
// ---------------------------------------------------------------------------
__global__ __launch_bounds__(256) void attn_mma()
{
    __shared__ float Kst[64][72];   // [d][j]
    __shared__ float Vst[64][68];   // [dv][j]

    int qt = 15 - blockIdx.x;     // big tiles first (load balance)
    int bh = blockIdx.y;
    int tid = threadIdx.x;
    int w = tid >> 5, lane = tid & 31;
    int g = lane >> 2, t4 = lane & 3;
    int q0 = qt * 128;

    int src_lo = (lane & ~3) | (t4 >> 1);
    int src_hi = src_lo + 2;
    bool odd = (t4 & 1) != 0;

    const float* Qp = g_Qf + (size_t)bh * T_ * HD_;
    const float* Kp = g_Kt + (size_t)bh * HD_ * T_;
    const float* Vp = g_Vt + (size_t)bh * HD_ * T_;

    int r0 = q0 + w * 16 + g;
    float qa[8][4];
    #pragma unroll
    for (int k = 0; k < 8; k++) {
        qa[k][0] = Qp[(size_t)r0 * HD_ + k * 8 + t4];
        qa[k][1] = Qp[(size_t)(r0 + 8) * HD_ + k * 8 + t4];
        qa[k][2] = Qp[(size_t)r0 * HD_ + k * 8 + t4 + 4];
        qa[k][3] = Qp[(size_t)(r0 + 8) * HD_ + k * 8 + t4 + 4];
    }

    float O[8][4];
    #pragma unroll
    for (int n = 0; n < 8; n++)
        #pragma unroll
        for (int c = 0; c < 4; c++) O[n][c] = 0.0f;
    float m0 = -1e30f, m1 = -1e30f, l0 = 0.0f, l1 = 0.0f;

    int nkt = 2 * (qt + 1);
    for (int kt = 0; kt < nkt; kt++) {
        int j0 = kt * 64;
        __syncthreads();

        #pragma unroll
        for (int i = 0; i < 4; i++) {
            int linear = i * 256 + tid;
            int row = linear >> 4, c4 = (linear & 15) << 2;
            *(float4*)&Kst[row][c4] = *(const float4*)&Kp[(size_t)row * T_ + j0 + c4];
            *(float4*)&Vst[row][c4] = *(const float4*)&Vp[(size_t)row * T_ + j0 + c4];
        }
        __syncthreads();

        float S[8][4];
        #pragma unroll
        for (int n = 0; n < 8; n++)
            #pragma unroll
            for (int c = 0; c < 4; c++) S[n][c] = 0.0f;

        #pragma unroll
        for (int k = 0; k < 8; k++) {
            #pragma unroll
            for (int n = 0; n < 8; n++) {
                float b0 = Kst[k * 8 + t4][n * 8 + g];
                float b1 = Kst[k * 8 + t4 + 4][n * 8 + g];
                mma_tf32(S[n], qa[k], b0, b1);
            }
        }

        if (kt >= nkt - 2) {
            int qi0 = r0, qi1 = r0 + 8;
            #pragma unroll
            for (int n = 0; n < 8; n++) {
                int j = j0 + 8 * n + 2 * t4;
                if (j     > qi0) S[n][0] = -1e30f;
                if (j + 1 > qi0) S[n][1] = -1e30f;
                if (j     > qi1) S[n][2] = -1e30f;
                if (j + 1 > qi1) S[n][3] = -1e30f;
            }
        }

        float vmax0 = -1e30f, vmax1 = -1e30f;
        #pragma unroll
        for (int n = 0; n < 8; n++) {
            vmax0 = fmaxf(vmax0, fmaxf(S[n][0], S[n][1]));
            vmax1 = fmaxf(vmax1, fmaxf(S[n][2], S[n][3]));
        }
        vmax0 = fmaxf(vmax0, __shfl_xor_sync(0xffffffffu, vmax0, 1));
        vmax0 = fmaxf(vmax0, __shfl_xor_sync(0xffffffffu, vmax0, 2));
        vmax1 = fmaxf(vmax1, __shfl_xor_sync(0xffffffffu, vmax1, 1));
        vmax1 = fmaxf(vmax1, __shfl_xor_sync(0xffffffffu, vmax1, 2));

        float nm0 = fmaxf(m0, vmax0);
        float nm1 = fmaxf(m1, vmax1);
        float fac0 = __expf(m0 - nm0);
        float fac1 = __expf(m1 - nm1);
        m0 = nm0; m1 = nm1;

        float rs0 = 0.0f, rs1 = 0.0f;
        #pragma unroll
        for (int n = 0; n < 8; n++) {
            float p00 = to_tf32(__expf(S[n][0] - nm0));
            float p01 = to_tf32(__expf(S[n][1] - nm0));
            float p10 = to_tf32(__expf(S[n][2] - nm1));
            float p11 = to_tf32(__expf(S[n][3] - nm1));
            rs0 += p00 + p01;
            rs1 += p10 + p11;
            S[n][0] = p00; S[n][1] = p01; S[n][2] = p10; S[n][3] = p11;
        }
        rs0 += __shfl_xor_sync(0xffffffffu, rs0, 1);
        rs0 += __shfl_xor_sync(0xffffffffu, rs0, 2);
        rs1 += __shfl_xor_sync(0xffffffffu, rs1, 1);
        rs1 += __shfl_xor_sync(0xffffffffu, rs1, 2);
        l0 = l0 * fac0 + rs0;
        l1 = l1 * fac1 + rs1;

        #pragma unroll
        for (int n = 0; n < 8; n++) {
            O[n][0] *= fac0; O[n][1] *= fac0;
            O[n][2] *= fac1; O[n][3] *= fac1;
        }

        #pragma unroll
        for (int kk = 0; kk < 8; kk++) {
            float p00 = S[kk][0], p01 = S[kk][1];
            float p10 = S[kk][2], p11 = S[kk][3];
            float x0 = __shfl_sync(0xffffffffu, p00, src_lo);
            float x1 = __shfl_sync(0xffffffffu, p01, src_lo);
            float y0 = __shfl_sync(0xffffffffu, p10, src_lo);
            float y1 = __shfl_sync(0xffffffffu, p11, src_lo);
            float z0 = __shfl_sync(0xffffffffu, p00, src_hi);
            float z1 = __shfl_sync(0xffffffffu, p01, src_hi);
            float u0 = __shfl_sync(0xffffffffu, p10, src_hi);
            float u1 = __shfl_sync(0xffffffffu, p11, src_hi);
            float a[4];
            a[0] = odd ? x1 : x0;
            a[1] = odd ? y1 : y0;
            a[2] = odd ? z1 : z0;
            a[3] = odd ? u1 : u0;
            #pragma unroll
            for (int n = 0; n < 8; n++) {
                float b0 = Vst[8 * n + g][8 * kk + t4];
                float b1 = Vst[8 * n + g][8 * kk + t4 + 4];
                mma_tf32(O[n], a, b0, b1);
            }
        }
    }

    // Epilogue: normalize, tf32-round (feeds tf32 out-GEMM), write g_A
    int b = bh >> 3, h = bh & 7;
    float inv0 = 1.0f / l0;
    float inv1 = 1.0f / l1;
    #pragma unroll
    for (int n = 0; n < 8; n++) {
        int dv = 8 * n + 2 * t4;
        float2 v0 = make_float2(to_tf32(O[n][0] * inv0), to_tf32(O[n][1] * inv0));
        float2 v1 = make_float2(to_tf32(O[n][2] * inv1), to_tf32(O[n][3] * inv1));
        *(float2*)&g_A[((size_t)b * T_ + r0)     * D_ + h * HD_ + dv] = v0;
        *(float2*)&g_A[((size_t)b * T_ + r0 + 8) * D_ + h * HD_ + dv] = v1;
    }
}

// ---------------------------------------------------------------------------
extern "C" void kernel_launch(void* const* d_in, const int* in_sizes, int n_in,
                              void* d_out, int out_size)
{
    const float* x     = (const float*)d_in[0];   // [4,2048,512]
    const float* W_qkv = (const float*)d_in[1];   // [512,1536]
    const float* b_qkv = (const float*)d_in[2];   // [1536]
    const float* W_out = (const float*)d_in[3];   // [512,512]
    const float* b_out = (const float*)d_in[4];   // [512]
    float* out = (float*)d_out;                   // [4,2048,512]

    gemm_tf32<1536, 1, false><<<dim3(12, 64), 256>>>(x, W_qkv, b_qkv, nullptr);
    attn_mma<<<dim3(16, 32), 256>>>();
    gemm_tf32<512, 0, true><<<dim3(4, 64), 256>>>(nullptr, W_out, b_out, out);
}

// round 6
// speedup vs baseline: 3.1473x; 1.2087x over previous
#include <cuda_runtime.h>
#include <cuda_bf16.h>

#define B_  4
#define T_  2048
#define D_  512
#define H_  8
#define HD_ 64
#define BH_ (B_*H_)   // 32

// Scratch (allocation-free rule: __device__ globals)
__device__ __align__(16) float g_Qf[BH_*T_*HD_];   // [b,h,t,hd] tf32, pre-scaled 0.125
__device__ __align__(16) float g_Kt[BH_*HD_*T_];   // [b,h,hd,t] tf32 (transposed)
__device__ __align__(16) float g_Vt[BH_*HD_*T_];   // [b,h,dv,t] tf32 (transposed)
__device__ __align__(16) float g_A [B_*T_*D_];     // attention out [b,t,D], tf32-rounded

__device__ __forceinline__ float to_tf32(float x) {
    float r;
    asm("cvt.rna.tf32.f32 %0, %1;" : "=f"(r) : "f"(x));
    return r;
}

__device__ __forceinline__ float4 to_tf32_4(float4 v) {
    return make_float4(to_tf32(v.x), to_tf32(v.y), to_tf32(v.z), to_tf32(v.w));
}

__device__ __forceinline__ void mma_tf32(float* c, const float* a, float b0, float b1) {
    asm volatile(
        "mma.sync.aligned.m16n8k8.row.col.f32.tf32.tf32.f32 "
        "{%0,%1,%2,%3},{%4,%5,%6,%7},{%8,%9},{%0,%1,%2,%3};"
        : "+f"(c[0]), "+f"(c[1]), "+f"(c[2]), "+f"(c[3])
        : "r"(__float_as_uint(a[0])), "r"(__float_as_uint(a[1])),
          "r"(__float_as_uint(a[2])), "r"(__float_as_uint(a[3])),
          "r"(__float_as_uint(b0)), "r"(__float_as_uint(b1)));
}

__device__ __forceinline__ void cp16(unsigned dst, const void* src) {
    asm volatile("cp.async.cg.shared.global [%0], [%1], 16;" :: "r"(dst), "l"(src));
}

// ===========================================================================
// tf32 mma GEMM: C[128x128] = A[128x512] * B[512x128] (+bias).
// 256 threads = 8 warps (4m x 2n), warp tile 32x64.
// Double-buffered smem, k-tile 16, register prefetch, ONE sync per k-tile.
// EPI: 0 = plain store + bias ; 1 = qkv scatter epilogue.
// A_GA: read A from device-global g_A inside device code (a __device__
//       symbol passed as a host-side kernel arg resolves to the host shadow).
// ===========================================================================
template<int N_GL, int EPI, bool A_GA>
__global__ __launch_bounds__(256, 2) void gemm_tf32(
    const float* __restrict__ A_in,
    const float* __restrict__ B_gl,
    const float* __restrict__ bias,
    float* __restrict__ out)
{
    const int K = 512;
    const float* A_gl = A_GA ? (const float*)g_A : A_in;

    __shared__ float As[2][128][20];   // [m][k] stride 20 (== 4 mod 32)
    __shared__ float Bs[2][16][136];   // [k][n] stride 136 (== 8 mod 32)

    int bm = blockIdx.y * 128, bn = blockIdx.x * 128;
    int tid = threadIdx.x;
    int w = tid >> 5, lane = tid & 31, g = lane >> 2, t4 = lane & 3;
    int wm = (w >> 1) * 32, wn = (w & 1) * 64;

    int ar = tid >> 1;               // 0..127
    int ak = (tid & 1) * 8;
    int br = tid >> 4;               // 0..15
    int bc = (tid & 15) * 8;

    const float* Ap = A_gl + (size_t)(bm + ar) * K + ak;
    const float* Bp = B_gl + (size_t)br * N_GL + bn + bc;

    float4 ra0 = *(const float4*)(Ap);
    float4 ra1 = *(const float4*)(Ap + 4);
    float4 rb0 = *(const float4*)(Bp);
    float4 rb1 = *(const float4*)(Bp + 4);

    float acc[2][8][4];
    #pragma unroll
    for (int mt = 0; mt < 2; mt++)
        #pragma unroll
        for (int nt = 0; nt < 8; nt++)
            #pragma unroll
            for (int c = 0; c < 4; c++) acc[mt][nt][c] = 0.0f;

    // prologue: stage tile 0 into buffer 0
    *(float4*)&As[0][ar][ak]     = to_tf32_4(ra0);
    *(float4*)&As[0][ar][ak + 4] = to_tf32_4(ra1);
    *(float4*)&Bs[0][br][bc]     = to_tf32_4(rb0);
    *(float4*)&Bs[0][br][bc + 4] = to_tf32_4(rb1);
    __syncthreads();

    #pragma unroll 1
    for (int kt = 0; kt < 32; kt++) {
        int cur = kt & 1;

        // prefetch next tile to registers (overlaps with compute below)
        if (kt < 31) {
            Ap += 16;
            Bp += (size_t)16 * N_GL;
            ra0 = *(const float4*)(Ap);
            ra1 = *(const float4*)(Ap + 4);
            rb0 = *(const float4*)(Bp);
            rb1 = *(const float4*)(Bp + 4);
        }

        // compute 2 k-steps of 8 from buffer cur
        #pragma unroll
        for (int ks = 0; ks < 2; ks++) {
            int k0 = ks * 8;
            float af[2][4];
            #pragma unroll
            for (int mt = 0; mt < 2; mt++) {
                af[mt][0] = As[cur][wm + mt * 16 + g][k0 + t4];
                af[mt][1] = As[cur][wm + mt * 16 + g + 8][k0 + t4];
                af[mt][2] = As[cur][wm + mt * 16 + g][k0 + t4 + 4];
                af[mt][3] = As[cur][wm + mt * 16 + g + 8][k0 + t4 + 4];
            }
            #pragma unroll
            for (int nt = 0; nt < 8; nt++) {
                float b0 = Bs[cur][k0 + t4][wn + nt * 8 + g];
                float b1 = Bs[cur][k0 + t4 + 4][wn + nt * 8 + g];
                mma_tf32(acc[0][nt], af[0], b0, b1);
                mma_tf32(acc[1][nt], af[1], b0, b1);
            }
        }

        // stage next tile into the other buffer (readers fenced last iter)
        if (kt < 31) {
            int nb = cur ^ 1;
            *(float4*)&As[nb][ar][ak]     = to_tf32_4(ra0);
            *(float4*)&As[nb][ar][ak + 4] = to_tf32_4(ra1);
            *(float4*)&Bs[nb][br][bc]     = to_tf32_4(rb0);
            *(float4*)&Bs[nb][br][bc + 4] = to_tf32_4(rb1);
        }
        __syncthreads();
    }

    // Epilogue
    #pragma unroll
    for (int mt = 0; mt < 2; mt++) {
        #pragma unroll
        for (int nt = 0; nt < 8; nt++) {
            #pragma unroll
            for (int c = 0; c < 4; c++) {
                int m = bm + wm + mt * 16 + g + ((c >> 1) ? 8 : 0);
                int n = bn + wn + nt * 8 + 2 * t4 + (c & 1);
                float v = acc[mt][nt][c] + bias[n];
                if (EPI == 0) {
                    out[(size_t)m * N_GL + n] = v;
                } else {
                    int b = m >> 11;
                    int t = m & (T_ - 1);
                    int which = n >> 9;     // 0=q, 1=k, 2=v
                    int r = n & 511;
                    int h = r >> 6, hd = r & 63;
                    int bh = b * H_ + h;
                    if (which == 0)
                        g_Qf[((size_t)bh * T_ + t) * HD_ + hd] = to_tf32(v * 0.125f);
                    else if (which == 1)
                        g_Kt[((size_t)bh * HD_ + hd) * T_ + t] = to_tf32(v);
                    else
                        g_Vt[((size_t)bh * HD_ + hd) * T_ + t] = to_tf32(v);
                }
            }
        }
    }
}

// ---------------------------------------------------------------------------
// Flash attention (causal), all-tf32 mma, cp.async double-buffered K/V.
// Grid: (qtile=16, bh=32). 256 threads = 8 warps; warp w owns Q rows
// [q0+16w, q0+16w+16). KV tiles of 64. Dynamic smem 71680 B.
// ---------------------------------------------------------------------------
#define KBUF_F (64*72)     // floats per K buffer
#define VBUF_F (64*68)
#define ATTN_SMEM ((2*KBUF_F + 2*VBUF_F)*4)

__global__ __launch_bounds__(256, 2) void attn_mma()
{
    extern __shared__ float dynsmem[];
    float* Kbuf = dynsmem;                 // [2][64][72]
    float* Vbuf = dynsmem + 2 * KBUF_F;    // [2][64][68]

    int qt = 15 - blockIdx.x;     // big tiles first (load balance)
    int bh = blockIdx.y;
    int tid = threadIdx.x;
    int w = tid >> 5, lane = tid & 31;
    int g = lane >> 2, t4 = lane & 3;
    int q0 = qt * 128;

    int src_lo = (lane & ~3) | (t4 >> 1);
    int src_hi = src_lo + 2;
    bool odd = (t4 & 1) != 0;

    const float* Qp = g_Qf + (size_t)bh * T_ * HD_;
    const float* Kp = g_Kt + (size_t)bh * HD_ * T_;
    const float* Vp = g_Vt + (size_t)bh * HD_ * T_;

    unsigned k_smem = (unsigned)__cvta_generic_to_shared(Kbuf);
    unsigned v_smem = (unsigned)__cvta_generic_to_shared(Vbuf);

    int ld_row = tid >> 4;                 // 0..15 (row base, +16 per i)
    int ld_c4  = (tid & 15) << 2;          // 0..60

    int r0 = q0 + w * 16 + g;
    float qa[8][4];
    #pragma unroll
    for (int k = 0; k < 8; k++) {
        qa[k][0] = Qp[(size_t)r0 * HD_ + k * 8 + t4];
        qa[k][1] = Qp[(size_t)(r0 + 8) * HD_ + k * 8 + t4];
        qa[k][2] = Qp[(size_t)r0 * HD_ + k * 8 + t4 + 4];
        qa[k][3] = Qp[(size_t)(r0 + 8) * HD_ + k * 8 + t4 + 4];
    }

    float O[8][4];
    #pragma unroll
    for (int n = 0; n < 8; n++)
        #pragma unroll
        for (int c = 0; c < 4; c++) O[n][c] = 0.0f;
    float m0 = -1e30f, m1 = -1e30f, l0 = 0.0f, l1 = 0.0f;

    int nkt = 2 * (qt + 1);

    // issue tile kt's K/V loads as cp.async (one commit group)
    auto issue_tile = [&](int kt) {
        int bb = kt & 1;
        int j0 = kt * 64;
        unsigned kb = k_smem + (unsigned)(bb * KBUF_F) * 4;
        unsigned vb = v_smem + (unsigned)(bb * VBUF_F) * 4;
        #pragma unroll
        for (int i = 0; i < 4; i++) {
            int row = ld_row + i * 16;
            cp16(kb + (unsigned)(row * 72 + ld_c4) * 4, Kp + (size_t)row * T_ + j0 + ld_c4);
            cp16(vb + (unsigned)(row * 68 + ld_c4) * 4, Vp + (size_t)row * T_ + j0 + ld_c4);
        }
        asm volatile("cp.async.commit_group;");
    };

    issue_tile(0);

    for (int kt = 0; kt < nkt; kt++) {
        int bb = kt & 1;
        if (kt + 1 < nkt) {
            issue_tile(kt + 1);
            asm volatile("cp.async.wait_group 1;");
        } else {
            asm volatile("cp.async.wait_group 0;");
        }
        __syncthreads();

        const float* Kb = Kbuf + bb * KBUF_F;   // [d][j] stride 72
        const float* Vb = Vbuf + bb * VBUF_F;   // [dv][j] stride 68
        int j0 = kt * 64;

        float S[8][4];
        #pragma unroll
        for (int n = 0; n < 8; n++)
            #pragma unroll
            for (int c = 0; c < 4; c++) S[n][c] = 0.0f;

        #pragma unroll
        for (int k = 0; k < 8; k++) {
            #pragma unroll
            for (int n = 0; n < 8; n++) {
                float b0 = Kb[(k * 8 + t4) * 72 + n * 8 + g];
                float b1 = Kb[(k * 8 + t4 + 4) * 72 + n * 8 + g];
                mma_tf32(S[n], qa[k], b0, b1);
            }
        }

        if (kt >= nkt - 2) {
            int qi0 = r0, qi1 = r0 + 8;
            #pragma unroll
            for (int n = 0; n < 8; n++) {
                int j = j0 + 8 * n + 2 * t4;
                if (j     > qi0) S[n][0] = -1e30f;
                if (j + 1 > qi0) S[n][1] = -1e30f;
                if (j     > qi1) S[n][2] = -1e30f;
                if (j + 1 > qi1) S[n][3] = -1e30f;
            }
        }

        float vmax0 = -1e30f, vmax1 = -1e30f;
        #pragma unroll
        for (int n = 0; n < 8; n++) {
            vmax0 = fmaxf(vmax0, fmaxf(S[n][0], S[n][1]));
            vmax1 = fmaxf(vmax1, fmaxf(S[n][2], S[n][3]));
        }
        vmax0 = fmaxf(vmax0, __shfl_xor_sync(0xffffffffu, vmax0, 1));
        vmax0 = fmaxf(vmax0, __shfl_xor_sync(0xffffffffu, vmax0, 2));
        vmax1 = fmaxf(vmax1, __shfl_xor_sync(0xffffffffu, vmax1, 1));
        vmax1 = fmaxf(vmax1, __shfl_xor_sync(0xffffffffu, vmax1, 2));

        float nm0 = fmaxf(m0, vmax0);
        float nm1 = fmaxf(m1, vmax1);
        float fac0 = __expf(m0 - nm0);
        float fac1 = __expf(m1 - nm1);
        m0 = nm0; m1 = nm1;

        float rs0 = 0.0f, rs1 = 0.0f;
        #pragma unroll
        for (int n = 0; n < 8; n++) {
            float p00 = to_tf32(__expf(S[n][0] - nm0));
            float p01 = to_tf32(__expf(S[n][1] - nm0));
            float p10 = to_tf32(__expf(S[n][2] - nm1));
            float p11 = to_tf32(__expf(S[n][3] - nm1));
            rs0 += p00 + p01;
            rs1 += p10 + p11;
            S[n][0] = p00; S[n][1] = p01; S[n][2] = p10; S[n][3] = p11;
        }
        rs0 += __shfl_xor_sync(0xffffffffu, rs0, 1);
        rs0 += __shfl_xor_sync(0xffffffffu, rs0, 2);
        rs1 += __shfl_xor_sync(0xffffffffu, rs1, 1);
        rs1 += __shfl_xor_sync(0xffffffffu, rs1, 2);
        l0 = l0 * fac0 + rs0;
        l1 = l1 * fac1 + rs1;

        #pragma unroll
        for (int n = 0; n < 8; n++) {
            O[n][0] *= fac0; O[n][1] *= fac0;
            O[n][2] *= fac1; O[n][3] *= fac1;
        }

        #pragma unroll
        for (int kk = 0; kk < 8; kk++) {
            float p00 = S[kk][0], p01 = S[kk][1];
            float p10 = S[kk][2], p11 = S[kk][3];
            float x0 = __shfl_sync(0xffffffffu, p00, src_lo);
            float x1 = __shfl_sync(0xffffffffu, p01, src_lo);
            float y0 = __shfl_sync(0xffffffffu, p10, src_lo);
            float y1 = __shfl_sync(0xffffffffu, p11, src_lo);
            float z0 = __shfl_sync(0xffffffffu, p00, src_hi);
            float z1 = __shfl_sync(0xffffffffu, p01, src_hi);
            float u0 = __shfl_sync(0xffffffffu, p10, src_hi);
            float u1 = __shfl_sync(0xffffffffu, p11, src_hi);
            float a[4];
            a[0] = odd ? x1 : x0;
            a[1] = odd ? y1 : y0;
            a[2] = odd ? z1 : z0;
            a[3] = odd ? u1 : u0;
            #pragma unroll
            for (int n = 0; n < 8; n++) {
                float b0 = Vb[(8 * n + g) * 68 + 8 * kk + t4];
                float b1 = Vb[(8 * n + g) * 68 + 8 * kk + t4 + 4];
                mma_tf32(O[n], a, b0, b1);
            }
        }
        __syncthreads();   // all reads of buffer bb done before it is refilled
    }

    // Epilogue: normalize, tf32-round (feeds tf32 out-GEMM), write g_A
    int b = bh >> 3, h = bh & 7;
    float inv0 = 1.0f / l0;
    float inv1 = 1.0f / l1;
    #pragma unroll
    for (int n = 0; n < 8; n++) {
        int dv = 8 * n + 2 * t4;
        float2 v0 = make_float2(to_tf32(O[n][0] * inv0), to_tf32(O[n][1] * inv0));
        float2 v1 = make_float2(to_tf32(O[n][2] * inv1), to_tf32(O[n][3] * inv1));
        *(float2*)&g_A[((size_t)b * T_ + r0)     * D_ + h * HD_ + dv] = v0;
        *(float2*)&g_A[((size_t)b * T_ + r0 + 8) * D_ + h * HD_ + dv] = v1;
    }
}

// ---------------------------------------------------------------------------
extern "C" void kernel_launch(void* const* d_in, const int* in_sizes, int n_in,
                              void* d_out, int out_size)
{
    const float* x     = (const float*)d_in[0];   // [4,2048,512]
    const float* W_qkv = (const float*)d_in[1];   // [512,1536]
    const float* b_qkv = (const float*)d_in[2];   // [1536]
    const float* W_out = (const float*)d_in[3];   // [512,512]
    const float* b_out = (const float*)d_in[4];   // [512]
    float* out = (float*)d_out;                   // [4,2048,512]

    cudaFuncSetAttribute(attn_mma, cudaFuncAttributeMaxDynamicSharedMemorySize, ATTN_SMEM);

    gemm_tf32<1536, 1, false><<<dim3(12, 64), 256>>>(x, W_qkv, b_qkv, nullptr);
    attn_mma<<<dim3(16, 32), 256, ATTN_SMEM>>>();
    gemm_tf32<512, 0, true><<<dim3(4, 64), 256>>>(nullptr, W_out, b_out, out);
}